// round 4
// baseline (speedup 1.0000x reference)
#include <cuda_runtime.h>
#include <cuda_bf16.h>

// HATS constants (fixed by the problem definition)
#define KCELL   10
#define RR      3
#define SSZ     7          // 2R+1
#define NBINS   98         // 2 * S * S
#define GWW     24         // W / K
#define NCELLS  432        // (H/K)*(W/K) = 18*24
#define TAU_INV (1.0f / 1e6f)
#define DT_MAX  1e5f
#define CAP     64         // max events per (batch, cell) bucket (mean ~4.7)
#define MAXB    16         // max batch supported by scratch
#define WPB     8          // warps per block in the cell kernel

// Scratch (device globals — zero-initialized at module load; the cell kernel
// re-zeros g_bcount after consuming it, so every graph replay starts clean).
__device__ int    g_bcount[MAXB * NCELLS];
__device__ float4 g_bev  [MAXB * NCELLS * CAP];
__device__ int    g_bidx [MAXB * NCELLS * CAP];

// ---------------------------------------------------------------------------
// Kernel 1: scatter valid events into per-(batch, cell) buckets.
// ---------------------------------------------------------------------------
__global__ void hats_build_buckets(const float4* __restrict__ ev,
                                   const int* __restrict__ lengths,
                                   int T, int total) {
    int g = blockIdx.x * blockDim.x + threadIdx.x;
    if (g >= total) return;
    int b = g / T;
    int i = g - b * T;
    if (i >= lengths[b]) return;
    float4 e = ev[g];
    int cell = ((int)e.y / KCELL) * GWW + ((int)e.x / KCELL);
    int gc = b * NCELLS + cell;
    int slot = atomicAdd(&g_bcount[gc], 1);
    if (slot < CAP) {
        g_bev[gc * CAP + slot] = e;
        g_bidx[gc * CAP + slot] = i;   // original index -> exact causality
    }
}

// ---------------------------------------------------------------------------
// Kernel 2: per-cell pairwise time-surface accumulation + fused normalize.
// One warp per (batch, cell). Writes ALL output bins (zeros for empty cells).
// Also resets g_bcount[gc] to 0, keeping scratch clean for the next replay.
// ---------------------------------------------------------------------------
__global__ void hats_cell_kernel(float* __restrict__ out, int ncells_total) {
    __shared__ float4 sev [WPB][CAP];
    __shared__ int    sidx[WPB][CAP];
    __shared__ float  hist[WPB][NBINS];

    int warp = threadIdx.x >> 5;
    int lane = threadIdx.x & 31;
    int gc = blockIdx.x * WPB + warp;        // (b * NCELLS + cell)
    if (gc >= ncells_total) return;

    int rawcnt = g_bcount[gc];
    if (lane == 0) g_bcount[gc] = 0;         // self-clean for next replay
    int n = rawcnt < CAP ? rawcnt : CAP;

    for (int k = lane; k < NBINS; k += 32) hist[warp][k] = 0.0f;
    for (int k = lane; k < n; k += 32) {
        sev [warp][k] = g_bev [gc * CAP + k];
        sidx[warp][k] = g_bidx[gc * CAP + k];
    }
    __syncwarp();

    int np = n * n;
    for (int p = lane; p < np; p += 32) {
        int a = p / n;                        // center event
        int c = p - a * n;                    // contributor
        if (sidx[warp][c] > sidx[warp][a]) continue;   // causal: j <= i
        float4 fa = sev[warp][a];
        float4 fb = sev[warp][c];
        float dt = fa.z - fb.z;               // >= 0 by causality + sorted t
        if (dt > DT_MAX) continue;
        int dx = (int)fb.x - (int)fa.x + RR;
        int dy = (int)fb.y - (int)fa.y + RR;
        if ((unsigned)dx < SSZ && (unsigned)dy < SSZ && fa.w == fb.w) {
            int bin = ((int)fa.w * SSZ + dy) * SSZ + dx;
            atomicAdd(&hist[warp][bin], __expf(-dt * TAU_INV));
        }
    }
    __syncwarp();

    float inv = 1.0f / fmaxf((float)rawcnt, 1.0f);
    float* obase = out + (size_t)gc * NBINS;
    for (int k = lane; k < NBINS; k += 32) obase[k] = hist[warp][k] * inv;
}

// ---------------------------------------------------------------------------
// Launch
// ---------------------------------------------------------------------------
extern "C" void kernel_launch(void* const* d_in, const int* in_sizes, int n_in,
                              void* d_out, int out_size) {
    const float4* ev = (const float4*)d_in[0];  // [B, T, 4] = (x, y, t, p)
    const int* lengths = (const int*)d_in[1];   // [B]
    float* out = (float*)d_out;                 // [B, NC, 2, S, S] float32

    int B = in_sizes[1];
    int T = in_sizes[0] / (4 * B);
    int nct = B * NCELLS;
    int total = B * T;

    {
        int threads = 256;
        hats_build_buckets<<<(total + threads - 1) / threads, threads>>>(
            ev, lengths, T, total);
    }
    {
        int blocks = (nct + WPB - 1) / WPB;
        hats_cell_kernel<<<blocks, WPB * 32>>>(out, nct);
    }
}